// round 4
// baseline (speedup 1.0000x reference)
#include <cuda_runtime.h>
#include <cuda_bf16.h>

#define NN 50000
#define EE 600000
#define NPART 196   // ceil(NN/256)

// ---------------- device scratch ----------------
__device__ __align__(16) float g_AB[NN * 128];
__device__ __align__(16) float g_deg[NN];
__device__ __align__(16) float g_dinv[NN];
__device__ __align__(16) float g_xl[NN * 128];
__device__ __align__(16) float g_x1[NN * 128];
__device__ __align__(16) float g_WTp[128 * 128];
__device__ __align__(16) float g_WT1[128 * 128];
__device__ __align__(16) float g_WT2[128 * 128];
__device__ __align__(16) int   g_src[EE];
__device__ __align__(16) int   g_dst[EE];
__device__ __align__(16) int   g_cnt[NN];
__device__ __align__(16) int   g_part[256];
__device__ __align__(16) int   g_row[NN + 1];
__device__ __align__(16) int   g_cur[NN];
__device__ __align__(16) int   g_csrc[EE];   // CSR: src per slot
__device__ __align__(16) int   g_cdst[EE];   // CSR: dst per slot
__device__ __align__(16) float g_cw[EE];     // CSR: coef per slot

// ---------------- init: zero cnt, deg=1 (self loop), k-major weights --------
__global__ void init_misc(const float* __restrict__ W_p1,
                          const float* __restrict__ W1,
                          const float* __restrict__ W2) {
    if (blockIdx.x < NPART) {
        int i = blockIdx.x * 256 + threadIdx.x;
        if (i < NN) { g_cnt[i] = 0; g_deg[i] = 1.0f; }
    } else {
        for (int idx = threadIdx.x; idx < 128 * 128; idx += 256) {
            int k = idx >> 7;
            int j = idx & 127;
            g_WT1[idx] = W1[j * 128 + k];
            g_WT2[idx] = W2[j * 128 + k];
            g_WTp[idx] = (j < 64) ? W_p1[j * 256 + k] : W_p1[(j - 64) * 256 + 128 + k];
        }
    }
}

// ---------------- edge conversion (dtype-robust) + dst histogram ----------------
__global__ void convert_edges(const int* __restrict__ raw) {
    bool is64 = true;
    #pragma unroll
    for (int i = 1; i < 128; i += 2)
        if (raw[i] != 0) { is64 = false; break; }
    int e = blockIdx.x * blockDim.x + threadIdx.x;
    if (e >= EE) return;
    int s, d;
    if (is64) { s = raw[2 * e];  d = raw[2 * (EE + e)]; }
    else      { s = raw[e];      d = raw[EE + e]; }
    g_src[e] = s;
    g_dst[e] = d;
    atomicAdd(&g_cnt[d], 1);
}

// ---------------- 3-kernel exclusive scan of g_cnt -> g_row, g_cur ----------------
__global__ void scan_part() {
    __shared__ int sm[256];
    int tid = threadIdx.x;
    int i = blockIdx.x * 256 + tid;
    sm[tid] = (i < NN) ? g_cnt[i] : 0;
    __syncthreads();
    for (int o = 128; o; o >>= 1) {
        if (tid < o) sm[tid] += sm[tid + o];
        __syncthreads();
    }
    if (tid == 0) g_part[blockIdx.x] = sm[0];
}

__global__ void scan_tops() {
    __shared__ int sm[256];
    int tid = threadIdx.x;
    int v = (tid < NPART) ? g_part[tid] : 0;
    sm[tid] = v;
    __syncthreads();
    for (int o = 1; o < 256; o <<= 1) {
        int t = sm[tid] + ((tid >= o) ? sm[tid - o] : 0);
        __syncthreads();
        sm[tid] = t;
        __syncthreads();
    }
    if (tid < NPART) g_part[tid] = sm[tid] - v;  // exclusive
}

__global__ void scan_final() {
    __shared__ int sm[256];
    int tid = threadIdx.x;
    int i = blockIdx.x * 256 + tid;
    int v = (i < NN) ? g_cnt[i] : 0;
    sm[tid] = v;
    __syncthreads();
    for (int o = 1; o < 256; o <<= 1) {
        int t = sm[tid] + ((tid >= o) ? sm[tid - o] : 0);
        __syncthreads();
        sm[tid] = t;
        __syncthreads();
    }
    if (i < NN) {
        int excl = sm[tid] - v + g_part[blockIdx.x];
        g_row[i] = excl;
        g_cur[i] = excl;
    }
    if (i == 0) g_row[NN] = EE;
}

// ---------------- persistent register-tiled SGEMM, 8x8 per thread -------------
// Y[M,128] = X[M,128] @ WT (k-major WT[k*128+j]).
// Block: 256 threads, tile 128 rows x 128 cols; weights in smem once.
__global__ void __launch_bounds__(256, 1)
gemm128(const float* __restrict__ X, const float* __restrict__ WT,
        float* __restrict__ Y, int M) {
    extern __shared__ float sm[];
    float* Ws = sm;            // 16384 floats (64KB)
    float* Xs = sm + 16384;    // 16384 floats (64KB)
    const int tid = threadIdx.x;

    const float4* WT4 = (const float4*)WT;
    float4* Ws4 = (float4*)Ws;
    #pragma unroll
    for (int i = tid; i < 4096; i += 256) Ws4[i] = WT4[i];

    const int tx = tid & 15;   // col group: cols tx*8 .. tx*8+7
    const int ty = tid >> 4;   // row group: rows ty*8 .. ty*8+7
    const int ntiles = (M + 127) >> 7;

    for (int tile = blockIdx.x; tile < ntiles; tile += gridDim.x) {
        const int row0 = tile << 7;
        __syncthreads();  // Ws ready / previous tile compute done
        const int rows = min(128, M - row0);
        const int n4 = rows * 32;
        const float4* X4 = (const float4*)(X + (size_t)row0 * 128);
        float4* Xs4 = (float4*)Xs;
        #pragma unroll
        for (int i = tid; i < 4096; i += 256)
            Xs4[i] = (i < n4) ? X4[i] : make_float4(0.f, 0.f, 0.f, 0.f);
        __syncthreads();

        float acc[8][8];
        #pragma unroll
        for (int i = 0; i < 8; i++)
            #pragma unroll
            for (int j = 0; j < 8; j++) acc[i][j] = 0.f;

        for (int k4 = 0; k4 < 32; k4++) {
            float4 xv[8];
            #pragma unroll
            for (int i = 0; i < 8; i++)
                xv[i] = *(const float4*)&Xs[(ty * 8 + i) * 128 + k4 * 4];
            #pragma unroll
            for (int kk = 0; kk < 4; kk++) {
                float4 wa = *(const float4*)&Ws[(k4 * 4 + kk) * 128 + tx * 8];
                float4 wb = *(const float4*)&Ws[(k4 * 4 + kk) * 128 + tx * 8 + 4];
                #pragma unroll
                for (int i = 0; i < 8; i++) {
                    float xs = (kk == 0) ? xv[i].x : (kk == 1) ? xv[i].y
                             : (kk == 2) ? xv[i].z : xv[i].w;
                    acc[i][0] += xs * wa.x;
                    acc[i][1] += xs * wa.y;
                    acc[i][2] += xs * wa.z;
                    acc[i][3] += xs * wa.w;
                    acc[i][4] += xs * wb.x;
                    acc[i][5] += xs * wb.y;
                    acc[i][6] += xs * wb.z;
                    acc[i][7] += xs * wb.w;
                }
            }
        }

        #pragma unroll
        for (int i = 0; i < 8; i++) {
            int r = row0 + ty * 8 + i;
            if (r < M) {
                *(float4*)&Y[(size_t)r * 128 + tx * 8] =
                    make_float4(acc[i][0], acc[i][1], acc[i][2], acc[i][3]);
                *(float4*)&Y[(size_t)r * 128 + tx * 8 + 4] =
                    make_float4(acc[i][4], acc[i][5], acc[i][6], acc[i][7]);
            }
        }
    }
}

// ------- fused edge pass: ew = sigmoid(relu(A[s]+B[d]+b).w2+b2); CSR fill; deg --
__global__ void edge_fused(const float* __restrict__ b_p1,
                           const float* __restrict__ W_p2,
                           const float* __restrict__ b_p2) {
    int e = (blockIdx.x * blockDim.x + threadIdx.x) >> 5;
    int lane = threadIdx.x & 31;
    if (e >= EE) return;
    int s = g_src[e];
    int d = g_dst[e];
    float2 a  = *(const float2*)&g_AB[(size_t)s * 128 + lane * 2];
    float2 b  = *(const float2*)&g_AB[(size_t)d * 128 + 64 + lane * 2];
    float2 bp = *(const float2*)&b_p1[lane * 2];
    float2 w2 = *(const float2*)&W_p2[lane * 2];
    float h0 = fmaxf(a.x + b.x + bp.x, 0.f);
    float h1 = fmaxf(a.y + b.y + bp.y, 0.f);
    float p = h0 * w2.x + h1 * w2.y;
    #pragma unroll
    for (int o = 16; o; o >>= 1) p += __shfl_xor_sync(0xffffffffu, p, o);
    if (lane == 0) {
        float v = 1.f / (1.f + expf(-(p + b_p2[0])));
        int slot = atomicAdd(&g_cur[d], 1);
        g_csrc[slot] = s;
        g_cdst[slot] = d;
        g_cw[slot]   = v;
        atomicAdd(&g_deg[d], v);
    }
}

__global__ void dinv_kernel() {
    int i = blockIdx.x * blockDim.x + threadIdx.x;
    if (i < NN) g_dinv[i] = rsqrtf(g_deg[i]);
}

__global__ void coef_kernel() {
    int j = blockIdx.x * blockDim.x + threadIdx.x;
    if (j >= EE) return;
    g_cw[j] *= g_dinv[g_csrc[j]] * g_dinv[g_cdst[j]];
}

// ---------------- conv (gather form) + relu: 2 nodes / 256-thread block --------
__global__ void conv_relu(const float* __restrict__ bias) {
    int n = blockIdx.x * 2 + (threadIdx.x >> 7);
    int f = threadIdx.x & 127;
    if (n >= NN) return;
    float di = g_dinv[n];
    float acc = bias[f] + di * di * g_xl[(size_t)n * 128 + f];
    int e0 = g_row[n], e1 = g_row[n + 1];
    for (int j = e0; j < e1; j++) {
        int s = g_csrc[j];
        float c = g_cw[j];
        acc += c * g_xl[(size_t)s * 128 + f];
    }
    g_x1[(size_t)n * 128 + f] = fmaxf(acc, 0.f);
}

// ---------------- conv2 + fused head: sigmoid(relu(agg) @ W_lin^T + b_lin) -----
__global__ void conv_head(const float* __restrict__ bias,
                          const float* __restrict__ W_lin,
                          const float* __restrict__ b_lin,
                          float* __restrict__ out) {
    __shared__ float2 red[256];
    int half = threadIdx.x >> 7;          // which node in this block
    int n = blockIdx.x * 2 + half;
    int f = threadIdx.x & 127;
    float v = 0.f;
    if (n < NN) {
        float di = g_dinv[n];
        float acc = bias[f] + di * di * g_xl[(size_t)n * 128 + f];
        int e0 = g_row[n], e1 = g_row[n + 1];
        for (int j = e0; j < e1; j++) {
            int s = g_csrc[j];
            float c = g_cw[j];
            acc += c * g_xl[(size_t)s * 128 + f];
        }
        v = fmaxf(acc, 0.f);
    }
    red[threadIdx.x] = make_float2(v * W_lin[f], v * W_lin[128 + f]);
    __syncthreads();
    #pragma unroll
    for (int o = 64; o; o >>= 1) {
        if (f < o) {
            red[threadIdx.x].x += red[threadIdx.x + o].x;
            red[threadIdx.x].y += red[threadIdx.x + o].y;
        }
        __syncthreads();
    }
    if (f == 0 && n < NN) {
        out[2 * n + 0] = 1.f / (1.f + expf(-(red[half * 128].x + b_lin[0])));
        out[2 * n + 1] = 1.f / (1.f + expf(-(red[half * 128].y + b_lin[1])));
    }
}

// ---------------- host ----------------
extern "C" void kernel_launch(void* const* d_in, const int* in_sizes, int n_in,
                              void* d_out, int out_size) {
    const float* x     = (const float*)d_in[0];
    const int*   ei    = (const int*)d_in[1];
    const float* W_p1  = (const float*)d_in[2];
    const float* b_p1  = (const float*)d_in[3];
    const float* W_p2  = (const float*)d_in[4];
    const float* b_p2  = (const float*)d_in[5];
    const float* W1    = (const float*)d_in[6];
    const float* b1    = (const float*)d_in[7];
    const float* W2    = (const float*)d_in[8];
    const float* b2    = (const float*)d_in[9];
    const float* W_lin = (const float*)d_in[10];
    const float* b_lin = (const float*)d_in[11];
    float* out = (float*)d_out;

    void *pAB, *pXL, *pX1, *pWTp, *pWT1, *pWT2;
    cudaGetSymbolAddress(&pAB,  g_AB);
    cudaGetSymbolAddress(&pXL,  g_xl);
    cudaGetSymbolAddress(&pX1,  g_x1);
    cudaGetSymbolAddress(&pWTp, g_WTp);
    cudaGetSymbolAddress(&pWT1, g_WT1);
    cudaGetSymbolAddress(&pWT2, g_WT2);

    const int GEMM_SMEM = 32768 * 4;  // 128KB
    cudaFuncSetAttribute(gemm128, cudaFuncAttributeMaxDynamicSharedMemorySize, GEMM_SMEM);

    const int GEMM_GRID  = 148;                       // persistent, 1 block/SM
    const int edge_blocks = (EE * 32 + 255) / 256;    // warp per edge
    const int e_blocks    = (EE + 255) / 256;
    const int n_blocks    = (NN + 255) / 256;
    const int conv_blocks = (NN + 1) / 2;

    // 0..4: CSR build + init
    init_misc<<<NPART + 1, 256>>>(W_p1, W1, W2);
    convert_edges<<<e_blocks, 256>>>(ei);
    scan_part<<<NPART, 256>>>();
    scan_tops<<<1, 256>>>();
    scan_final<<<NPART, 256>>>();

    // 5: edge MLP factorized table (profiled launch)
    gemm128<<<GEMM_GRID, 256, GEMM_SMEM>>>(x, (const float*)pWTp, (float*)pAB, NN);
    // 6..8: edge weights + CSR + normalization
    edge_fused<<<edge_blocks, 256>>>(b_p1, W_p2, b_p2);
    dinv_kernel<<<n_blocks, 256>>>();
    coef_kernel<<<e_blocks, 256>>>();

    // 9..10: conv1
    gemm128<<<GEMM_GRID, 256, GEMM_SMEM>>>(x, (const float*)pWT1, (float*)pXL, NN);
    conv_relu<<<conv_blocks, 256>>>(b1);

    // 11..12: conv2 + head
    gemm128<<<GEMM_GRID, 256, GEMM_SMEM>>>((const float*)pX1, (const float*)pWT2, (float*)pXL, NN);
    conv_head<<<conv_blocks, 256>>>(b2, W_lin, b_lin, out);
}